// round 13
// baseline (speedup 1.0000x reference)
#include <cuda_runtime.h>
#include <cuda_bf16.h>
#include <cstdint>

// Problem constants
#define Bq   4
#define Sq   1023
#define SK   1024
#define EMB  1024
#define NH   16
#define HD   64
#define MTOT (Bq*Sq)        // 4092
#define MPAD 4096

// -------- scratch (device globals; no runtime allocation allowed) --------
// bf16 hi/lo split operands for tensor-core GEMMs
__device__ __nv_bfloat16 g_Ahi [MPAD*EMB],   g_Alo [MPAD*EMB];    // word states
__device__ __nv_bfloat16 g_Wqhi[3*EMB*EMB],  g_Wqlo[3*EMB*EMB];   // c_attn_w^T  [n][k]
__device__ __nv_bfloat16 g_Wphi[EMB*EMB],    g_Wplo[EMB*EMB];     // c_proj_w^T  [n][k]
__device__ __nv_bfloat16 g_AOhi[MPAD*EMB],   g_AOlo[MPAD*EMB];    // attn output
// bf16 hi/lo Q/K/V for tensor attention  [b][h][s|k][d]
__device__ __nv_bfloat16 g_Qh[Bq*NH*Sq*HD],  g_Ql[Bq*NH*Sq*HD];
__device__ __nv_bfloat16 g_Kh[Bq*NH*SK*HD],  g_Kl[Bq*NH*SK*HD];
__device__ __nv_bfloat16 g_Vh[Bq*NH*SK*HD],  g_Vl[Bq*NH*SK*HD];

// ===================== PTX helpers (compute_103-safe: sm_80 era) =====================
__device__ __forceinline__ uint32_t smem_u32(const void* p) {
    uint32_t a;
    asm("{ .reg .u64 t; cvta.to.shared.u64 t, %1; cvt.u32.u64 %0, t; }"
        : "=r"(a) : "l"(p));
    return a;
}

__device__ __forceinline__ void cp16(uint32_t dst, const void* src) {
    asm volatile("cp.async.cg.shared.global [%0], [%1], 16;"
                 :: "r"(dst), "l"(src) : "memory");
}
__device__ __forceinline__ void cp16z(uint32_t dst, const void* src, bool v) {
    int sz = v ? 16 : 0;
    asm volatile("cp.async.cg.shared.global [%0], [%1], 16, %2;"
                 :: "r"(dst), "l"(src), "r"(sz) : "memory");
}
#define CP_COMMIT() asm volatile("cp.async.commit_group;" ::: "memory")
#define CP_WAIT0()  asm volatile("cp.async.wait_group 0;" ::: "memory")
#define CP_WAIT1()  asm volatile("cp.async.wait_group 1;" ::: "memory")

__device__ __forceinline__ void ldm4(uint32_t* r, uint32_t addr) {
    asm volatile("ldmatrix.sync.aligned.m8n8.x4.shared.b16 {%0,%1,%2,%3}, [%4];"
                 : "=r"(r[0]), "=r"(r[1]), "=r"(r[2]), "=r"(r[3]) : "r"(addr));
}
__device__ __forceinline__ void ldm4t(uint32_t* r, uint32_t addr) {
    asm volatile("ldmatrix.sync.aligned.m8n8.x4.trans.shared.b16 {%0,%1,%2,%3}, [%4];"
                 : "=r"(r[0]), "=r"(r[1]), "=r"(r[2]), "=r"(r[3]) : "r"(addr));
}

__device__ __forceinline__ void mma16816(float* c, const uint32_t* a, const uint32_t* b) {
    asm volatile(
        "mma.sync.aligned.m16n8k16.row.col.f32.bf16.bf16.f32 "
        "{%0,%1,%2,%3}, {%4,%5,%6,%7}, {%8,%9}, {%0,%1,%2,%3};"
        : "+f"(c[0]), "+f"(c[1]), "+f"(c[2]), "+f"(c[3])
        : "r"(a[0]), "r"(a[1]), "r"(a[2]), "r"(a[3]), "r"(b[0]), "r"(b[1]));
}

// fast e^x on the FMA pipe (x <= ~0; rel err ~2e-6); avoids MUFU throughput floor
__device__ __forceinline__ float fexp(float x) {
    float y = fmaxf(x * 1.4426950408889634f, -126.0f);
    int   n = __float2int_rn(y);
    float f = y - (float)n;
    float p = 1.3333558146e-3f;
    p = fmaf(p, f, 9.6181291076e-3f);
    p = fmaf(p, f, 5.5504108664e-2f);
    p = fmaf(p, f, 2.4022650696e-1f);
    p = fmaf(p, f, 6.9314718056e-1f);
    p = fmaf(p, f, 1.0f);
    return p * __int_as_float((n + 127) << 23);
}

// split a pair of fp32 into bf16 hi / lo packed registers (.x = first arg = low half)
__device__ __forceinline__ void split2(float a, float b, uint32_t& hi, uint32_t& lo) {
    __nv_bfloat162 h = __floats2bfloat162_rn(a, b);
    __nv_bfloat162 l = __floats2bfloat162_rn(a - __bfloat162float(h.x),
                                             b - __bfloat162float(h.y));
    hi = *(uint32_t*)&h;
    lo = *(uint32_t*)&l;
}

// =====================================================================
// Convert kernels (fp32 -> bf16 hi/lo split)
// =====================================================================
__global__ __launch_bounds__(256)
void conva_kernel(const float* __restrict__ word)
{
    const int idx = blockIdx.x * 256 + threadIdx.x;   // MPAD*EMB/4 threads
    const int m = idx >> 8;
    const int c = (idx & 255) * 4;
    float4 v = make_float4(0.f, 0.f, 0.f, 0.f);
    if (m < MTOT) v = *(const float4*)&word[(size_t)m * EMB + c];
    const size_t o = (size_t)m * EMB + c;
    uint32_t h0, l0, h1, l1;
    split2(v.x, v.y, h0, l0);
    split2(v.z, v.w, h1, l1);
    *(uint32_t*)&g_Ahi[o]     = h0;
    *(uint32_t*)&g_Ahi[o + 2] = h1;
    *(uint32_t*)&g_Alo[o]     = l0;
    *(uint32_t*)&g_Alo[o + 2] = l1;
}

// transpose + convert: W[K=1024][N] -> Dhi/Dlo[N][1024]
__global__ __launch_bounds__(256)
void wconv_kernel(const float* __restrict__ W, int N, int mode)
{
    __shared__ float t[32][33];
    const int nx = blockIdx.x * 32, ky = blockIdx.y * 32;
    const int tx = threadIdx.x, ty = threadIdx.y;
    #pragma unroll
    for (int i = 0; i < 32; i += 8)
        t[ty + i][tx] = W[(size_t)(ky + ty + i) * N + nx + tx];
    __syncthreads();
    __nv_bfloat16* Dh = mode ? g_Wphi : g_Wqhi;
    __nv_bfloat16* Dl = mode ? g_Wplo : g_Wqlo;
    #pragma unroll
    for (int i = 0; i < 32; i += 8) {
        const float v = t[tx][ty + i];
        const int n = nx + ty + i, k = ky + tx;
        const __nv_bfloat16 h = __float2bfloat16(v);
        Dh[(size_t)n * EMB + k] = h;
        Dl[(size_t)n * EMB + k] = __float2bfloat16(v - __bfloat162float(h));
    }
}

__global__ __launch_bounds__(256)
void pad_ao_kernel()
{
    const int i = blockIdx.x * 256 + threadIdx.x;     // (MPAD-MTOT) rows * 1024
    if (i < (MPAD - MTOT) * EMB) {
        g_AOhi[(size_t)MTOT * EMB + i] = __float2bfloat16(0.f);
        g_AOlo[(size_t)MTOT * EMB + i] = __float2bfloat16(0.f);
    }
}

// =====================================================================
// mma.sync bf16 split GEMM: 128x128 CTA tile, BK=32, 8 warps (32x64 each).
// 3-stage cp.async pipeline (wait_group 1 -> wait only the older copy).
// mode 0: qkv (scatter bf16 hi/lo into g_Q*/g_K*/g_V*); mode 1: proj -> out.
// =====================================================================
#define GBK   32
#define GSTR  40
#define MATB  (128 * GSTR * 2)
#define BUFB  (4 * MATB)             // 40960
#define NSTG  3
#define GSMEM (NSTG * BUFB)          // 122880
#define NCH   (EMB / GBK)

__device__ __forceinline__ void gload(uint32_t dstbase, int tid, int k0, int bm, int bn,
                                      const __nv_bfloat16* __restrict__ Ahi,
                                      const __nv_bfloat16* __restrict__ Alo,
                                      const __nv_bfloat16* __restrict__ Bhi,
                                      const __nv_bfloat16* __restrict__ Blo)
{
    #pragma unroll
    for (int t = 0; t < 8; t++) {
        const int i   = tid + t * 256;
        const int mat = i >> 9;
        const int r   = (i >> 2) & 127;
        const int seg = i & 3;
        const uint32_t dst = dstbase + mat * MATB + r * (GSTR * 2) + seg * 16;
        const __nv_bfloat16* src = (mat == 0) ? Ahi : (mat == 1) ? Alo
                                 : (mat == 2) ? Bhi : Blo;
        const int grow = ((mat < 2) ? bm : bn) + r;
        cp16(dst, src + (size_t)grow * EMB + k0 + seg * 8);
    }
    CP_COMMIT();
}

__global__ __launch_bounds__(256)
void gemm_mma_kernel(const float* __restrict__ bias, float* __restrict__ out, int mode)
{
    extern __shared__ __nv_bfloat16 smg[];
    const uint32_t sb = smem_u32(smg);

    const int tid  = threadIdx.x;
    const int warp = tid >> 5;
    const int lane = tid & 31;
    const int bn = blockIdx.x * 128;
    const int bm = blockIdx.y * 128;
    const int wm = (warp & 3) * 32;
    const int wn = (warp >> 2) * 64;

    const __nv_bfloat16* Ahi = mode ? g_AOhi : g_Ahi;
    const __nv_bfloat16* Alo = mode ? g_AOlo : g_Alo;
    const __nv_bfloat16* Bhi = mode ? g_Wphi : g_Wqhi;
    const __nv_bfloat16* Blo = mode ? g_Wplo : g_Wqlo;

    float acc[2][8][4];
    #pragma unroll
    for (int i = 0; i < 2; i++)
        #pragma unroll
        for (int j = 0; j < 8; j++)
            #pragma unroll
            for (int k = 0; k < 4; k++) acc[i][j][k] = 0.0f;

    // prime 2 stages
    gload(sb,        tid, 0,   bm, bn, Ahi, Alo, Bhi, Blo);
    gload(sb + BUFB, tid, GBK, bm, bn, Ahi, Alo, Bhi, Blo);

    int bufc = 0;                     // buffer index of chunk c
    for (int c = 0; c < NCH; c++) {
        if (c + 2 < NCH) CP_WAIT1(); else CP_WAIT0();
        __syncthreads();
        if (c + 2 < NCH) {
            int bl = bufc + 2; if (bl >= NSTG) bl -= NSTG;
            gload(sb + bl * BUFB, tid, (c + 2) * GBK, bm, bn, Ahi, Alo, Bhi, Blo);
        }

        const uint32_t cb = sb + bufc * BUFB;
        if (++bufc == NSTG) bufc = 0;

        #pragma unroll
        for (int ks = 0; ks < GBK; ks += 16) {
            uint32_t ahi[2][4], alo[2][4], bhi[8][2], blo[8][2];
            #pragma unroll
            for (int mt = 0; mt < 2; mt++) {
                const uint32_t ra = cb + (wm + mt * 16 + (lane & 15)) * (GSTR * 2)
                                       + (ks + (lane >> 4) * 8) * 2;
                ldm4(ahi[mt], ra);
                ldm4(alo[mt], ra + MATB);
            }
            #pragma unroll
            for (int p = 0; p < 4; p++) {
                const uint32_t rowb = wn + p * 16 + (lane & 7) + ((lane >> 4) << 3);
                const uint32_t rb = cb + 2 * MATB + rowb * (GSTR * 2)
                                       + (ks + ((lane >> 3) & 1) * 8) * 2;
                uint32_t r4[4];
                ldm4(r4, rb);
                bhi[p*2][0] = r4[0]; bhi[p*2][1] = r4[1];
                bhi[p*2+1][0] = r4[2]; bhi[p*2+1][1] = r4[3];
                ldm4(r4, rb + MATB);
                blo[p*2][0] = r4[0]; blo[p*2][1] = r4[1];
                blo[p*2+1][0] = r4[2]; blo[p*2+1][1] = r4[3];
            }
            #pragma unroll
            for (int mt = 0; mt < 2; mt++)
                #pragma unroll
                for (int nt = 0; nt < 8; nt++) {
                    mma16816(acc[mt][nt], ahi[mt], bhi[nt]);
                    mma16816(acc[mt][nt], alo[mt], bhi[nt]);
                    mma16816(acc[mt][nt], ahi[mt], blo[nt]);
                }
        }
    }

    // ---- epilogue ----
    #pragma unroll
    for (int mt = 0; mt < 2; mt++) {
        #pragma unroll
        for (int nt = 0; nt < 8; nt++) {
            const int n = bn + wn + nt * 8 + (lane & 3) * 2;
            const float2 bv = *(const float2*)&bias[n];
            #pragma unroll
            for (int half = 0; half < 2; half++) {
                const int m = bm + wm + mt * 16 + (lane >> 2) + half * 8;
                if (m >= MTOT) continue;
                float2 v = make_float2(acc[mt][nt][half*2+0] + bv.x,
                                       acc[mt][nt][half*2+1] + bv.y);
                if (mode == 0) {
                    const int b_ = m / Sq;
                    const int s  = m - b_ * Sq;
                    const int sec = n >> 10;
                    const int e = n & 1023, h = e >> 6, d = e & 63;
                    uint32_t hu, lu;
                    split2(v.x, v.y, hu, lu);
                    size_t off;
                    __nv_bfloat16 *dh, *dl;
                    if (sec == 0) {
                        off = ((size_t)(b_ * NH + h) * Sq + s) * HD + d;
                        dh = g_Qh; dl = g_Ql;
                    } else if (sec == 1) {
                        off = ((size_t)(b_ * NH + h) * SK + s + 1) * HD + d;
                        dh = g_Kh; dl = g_Kl;
                    } else {
                        off = ((size_t)(b_ * NH + h) * SK + s + 1) * HD + d;
                        dh = g_Vh; dl = g_Vl;
                    }
                    *(uint32_t*)&dh[off] = hu;
                    *(uint32_t*)&dl[off] = lu;
                } else {
                    *(float2*)&out[(size_t)m * EMB + n] = v;
                }
            }
        }
    }
}

// =====================================================================
// image k/v -> key/value slot 0, bf16 hi/lo
// =====================================================================
__global__ __launch_bounds__(256)
void imgkv_kernel(const float* __restrict__ img,
                  const float* __restrict__ ukw, const float* __restrict__ ukb,
                  const float* __restrict__ uvw, const float* __restrict__ uvb)
{
    const int warp = threadIdx.x >> 5;
    const int lane = threadIdx.x & 31;
    const int idx  = blockIdx.x * 8 + warp;
    const int kv   = idx >> 12;
    const int rem  = idx & 4095;
    const int b    = rem >> 10;
    const int e    = rem & 1023;

    const float* w = (kv == 0 ? ukw : uvw) + (size_t)e * EMB;
    const float* x = img + (size_t)b * EMB;

    float s = 0.0f;
    #pragma unroll
    for (int t = 0; t < 8; t++) {
        const int f = (lane + t * 32) * 4;
        float4 wv = *(const float4*)&w[f];
        float4 xv = *(const float4*)&x[f];
        s = fmaf(wv.x, xv.x, s);
        s = fmaf(wv.y, xv.y, s);
        s = fmaf(wv.z, xv.z, s);
        s = fmaf(wv.w, xv.w, s);
    }
    #pragma unroll
    for (int off = 16; off >= 1; off >>= 1)
        s += __shfl_xor_sync(0xffffffffu, s, off, 32);

    if (lane == 0) {
        const float v = s + (kv == 0 ? ukb : uvb)[e];
        const int h = e >> 6, d = e & 63;
        const size_t off = ((size_t)(b * NH + h) * SK + 0) * HD + d;
        const __nv_bfloat16 hh = __float2bfloat16(v);
        const __nv_bfloat16 ll = __float2bfloat16(v - __bfloat162float(hh));
        if (kv == 0) { g_Kh[off] = hh; g_Kl[off] = ll; }
        else         { g_Vh[off] = hh; g_Vl[off] = ll; }
    }
}

// =====================================================================
// tensor-core flash attention (split bf16, 3-pass QK^T and PV).
// CTA: 128 threads = 4 warps, 64 queries; stream 64-key tiles.
// =====================================================================
#define ASTR    72
#define ATILE_B (64 * ASTR * 2)      // 9216
#define ATTN_SMEM (10 * ATILE_B)     // 92160

__device__ __forceinline__ void attn_ldkv(uint32_t dst, int tid, int kb,
    const __nv_bfloat16* __restrict__ Khp, const __nv_bfloat16* __restrict__ Klp,
    const __nv_bfloat16* __restrict__ Vhp, const __nv_bfloat16* __restrict__ Vlp)
{
    #pragma unroll
    for (int t = 0; t < 16; t++) {
        const int i   = tid + t * 128;      // 0..2047
        const int mat = i >> 9;             // 0..3
        const int r   = (i >> 3) & 63;
        const int seg = i & 7;
        const __nv_bfloat16* src =
            (mat == 0 ? Khp : mat == 1 ? Klp : mat == 2 ? Vhp : Vlp)
            + (size_t)(kb + r) * HD + seg * 8;
        cp16(dst + mat * ATILE_B + r * (ASTR * 2) + seg * 16, src);
    }
    CP_COMMIT();
}

__global__ __launch_bounds__(128)
void attn_kernel(const float* __restrict__ am)
{
    extern __shared__ char smA[];
    const uint32_t sb = smem_u32(smA);

    const int b  = blockIdx.z;
    const int h  = blockIdx.y;
    const int qt = (int)(gridDim.x - 1) - (int)blockIdx.x;   // heavy tiles first
    const int tid  = threadIdx.x;
    const int warp = tid >> 5;
    const int lane = tid & 31;
    const int q4 = lane & 3;
    const int r8 = lane >> 2;
    const int wm = warp * 16;
    const int q0 = qt * 64;
    const int bh = b * NH + h;
    const int bSq = b * Sq;

    const __nv_bfloat16* Khp = g_Kh + (size_t)bh * SK * HD;
    const __nv_bfloat16* Klp = g_Kl + (size_t)bh * SK * HD;
    const __nv_bfloat16* Vhp = g_Vh + (size_t)bh * SK * HD;
    const __nv_bfloat16* Vlp = g_Vl + (size_t)bh * SK * HD;

    // --- load Q tile (hi/lo) + first K/V tile ---
    #pragma unroll
    for (int t = 0; t < 8; t++) {
        const int i   = tid + t * 128;      // 0..1023
        const int mat = i >> 9;             // 0..1
        const int r   = (i >> 3) & 63;
        const int seg = i & 7;
        const int row = q0 + r;
        const bool v = row < Sq;
        const __nv_bfloat16* src = (mat ? g_Ql : g_Qh)
            + ((size_t)bh * Sq + (v ? row : 0)) * HD + seg * 8;
        cp16z(sb + mat * ATILE_B + r * (ASTR * 2) + seg * 16, src, v);
    }
    attn_ldkv(sb + 2 * ATILE_B, tid, 0, Khp, Klp, Vhp, Vlp);
    CP_WAIT0();
    __syncthreads();

    // Q fragments (A operand, m16k16 x4 ksteps), loaded once
    uint32_t qhi[4][4], qlo[4][4];
    #pragma unroll
    for (int kk = 0; kk < 4; kk++) {
        const uint32_t ra = sb + (wm + (lane & 15)) * (ASTR * 2)
                               + (kk * 16 + (lane >> 4) * 8) * 2;
        ldm4(qhi[kk], ra);
        ldm4(qlo[kk], ra + ATILE_B);
    }

    float o[8][4];
    #pragma unroll
    for (int i = 0; i < 8; i++)
        #pragma unroll
        for (int j = 0; j < 4; j++) o[i][j] = 0.0f;
    float m0 = -1e30f, m1 = -1e30f, l0 = 0.0f, l1 = 0.0f;

    const int ntl = min(16, qt + 2);
    const int i0 = q0 + wm + r8;
    const int i1 = i0 + 8;

    for (int c = 0; c < ntl; c++) {
        const uint32_t B0 = sb + 2 * ATILE_B + (c & 1) * (4 * ATILE_B);
        if (c + 1 < ntl)
            attn_ldkv(sb + 2 * ATILE_B + ((c + 1) & 1) * (4 * ATILE_B),
                      tid, (c + 1) * 64, Khp, Klp, Vhp, Vlp);
        const int kb = c * 64;

        // ---- S = Q K^T (3-pass split) ----
        float s[8][4];
        #pragma unroll
        for (int i = 0; i < 8; i++)
            #pragma unroll
            for (int j = 0; j < 4; j++) s[i][j] = 0.0f;

        #pragma unroll
        for (int kk = 0; kk < 4; kk++) {
            uint32_t kbh[8][2], kbl[8][2];
            #pragma unroll
            for (int p = 0; p < 4; p++) {
                const uint32_t rb = B0
                    + (p * 16 + (lane & 7) + ((lane >> 4) << 3)) * (ASTR * 2)
                    + (kk * 16 + ((lane >> 3) & 1) * 8) * 2;
                uint32_t r4[4];
                ldm4(r4, rb);
                kbh[p*2][0] = r4[0]; kbh[p*2][1] = r4[1];
                kbh[p*2+1][0] = r4[2]; kbh[p*2+1][1] = r4[3];
                ldm4(r4, rb + ATILE_B);
                kbl[p*2][0] = r4[0]; kbl[p*2][1] = r4[1];
                kbl[p*2+1][0] = r4[2]; kbl[p*2+1][1] = r4[3];
            }
            #pragma unroll
            for (int nt = 0; nt < 8; nt++) {
                mma16816(s[nt], qhi[kk], kbh[nt]);
                mma16816(s[nt], qlo[kk], kbh[nt]);
                mma16816(s[nt], qhi[kk], kbl[nt]);
            }
        }

        // ---- scale + mask + online softmax ----
        const bool domask = (c >= qt);
        float tm0 = -1e30f, tm1 = -1e30f;
        #pragma unroll
        for (int nt = 0; nt < 8; nt++) {
            const int j0 = kb + nt * 8 + 2 * q4;
            const float a0 = (j0 == 0) ? 0.0f : am[bSq + j0 - 1];
            const float a1 = am[bSq + j0];                 // col j0+1
            float v0 = fmaf(s[nt][0], 0.125f, a0);
            float v1 = fmaf(s[nt][1], 0.125f, a1);
            float v2 = fmaf(s[nt][2], 0.125f, a0);
            float v3 = fmaf(s[nt][3], 0.125f, a1);
            if (domask) {
                if (j0     > i0 + 1) v0 = -10000.0f + a0;
                if (j0 + 1 > i0 + 1) v1 = -10000.0f + a1;
                if (j0     > i1 + 1) v2 = -10000.0f + a0;
                if (j0 + 1 > i1 + 1) v3 = -10000.0f + a1;
            }
            s[nt][0] = v0; s[nt][1] = v1; s[nt][2] = v2; s[nt][3] = v3;
            tm0 = fmaxf(tm0, fmaxf(v0, v1));
            tm1 = fmaxf(tm1, fmaxf(v2, v3));
        }
        tm0 = fmaxf(tm0, __shfl_xor_sync(0xffffffffu, tm0, 1, 32));
        tm0 = fmaxf(tm0, __shfl_xor_sync(0xffffffffu, tm0, 2, 32));
        tm1 = fmaxf(tm1, __shfl_xor_sync(0xffffffffu, tm1, 1, 32));
        tm1 = fmaxf(tm1, __shfl_xor_sync(0xffffffffu, tm1, 2, 32));

        const float nm0 = fmaxf(m0, tm0), nm1 = fmaxf(m1, tm1);
        const float cor0 = fexp(m0 - nm0), cor1 = fexp(m1 - nm1);
        m0 = nm0; m1 = nm1;

        float rs0 = 0.0f, rs1 = 0.0f;
        #pragma unroll
        for (int nt = 0; nt < 8; nt++) {
            s[nt][0] = fexp(s[nt][0] - m0);
            s[nt][1] = fexp(s[nt][1] - m0);
            s[nt][2] = fexp(s[nt][2] - m1);
            s[nt][3] = fexp(s[nt][3] - m1);
            rs0 += s[nt][0] + s[nt][1];
            rs1 += s[nt][2] + s[nt][3];
        }
        rs0 += __shfl_xor_sync(0xffffffffu, rs0, 1, 32);
        rs0 += __shfl_xor_sync(0xffffffffu, rs0, 2, 32);
        rs1 += __shfl_xor_sync(0xffffffffu, rs1, 1, 32);
        rs1 += __shfl_xor_sync(0xffffffffu, rs1, 2, 32);
        l0 = l0 * cor0 + rs0;
        l1 = l1 * cor1 + rs1;
        #pragma unroll
        for (int nt = 0; nt < 8; nt++) {
            o[nt][0] *= cor0; o[nt][1] *= cor0;
            o[nt][2] *= cor1; o[nt][3] *= cor1;
        }

        // ---- pack P into A fragments (hi/lo) ----
        uint32_t phi[4][4], plo[4][4];
        #pragma unroll
        for (int kk = 0; kk < 4; kk++) {
            split2(s[2*kk][0],   s[2*kk][1],   phi[kk][0], plo[kk][0]);
            split2(s[2*kk][2],   s[2*kk][3],   phi[kk][1], plo[kk][1]);
            split2(s[2*kk+1][0], s[2*kk+1][1], phi[kk][2], plo[kk][2]);
            split2(s[2*kk+1][2], s[2*kk+1][3], phi[kk][3], plo[kk][3]);
        }

        // ---- O += P V (3-pass split), V via ldmatrix.trans ----
        const uint32_t Vb = B0 + 2 * ATILE_B;
        #pragma unroll
        for (int kk = 0; kk < 4; kk++) {
            #pragma unroll
            for (int np = 0; np < 4; np++) {
                const uint32_t va = Vb + (kk * 16 + (lane & 15)) * (ASTR * 2)
                                       + (np * 16 + (lane >> 4) * 8) * 2;
                uint32_t r4[4];
                ldm4t(r4, va);                       // Vhi
                {
                    uint32_t b0[2] = { r4[0], r4[1] };
                    uint32_t b1[2] = { r4[2], r4[3] };
                    mma16816(o[np*2],   phi[kk], b0);
                    mma16816(o[np*2+1], phi[kk], b1);
                    mma16816(o[np*2],   plo[kk], b0);
                    mma16816(o[np*2+1], plo[kk], b1);
                }
                ldm4t(r4, va + ATILE_B);             // Vlo
                {
                    uint32_t b0[2] = { r4[0], r4[1] };
                    uint32_t b1[2] = { r4[2], r4[3] };
                    mma16816(o[np*2],   phi[kk], b0);
                    mma16816(o[np*2+1], phi[kk], b1);
                }
            }
        }

        if (c + 1 < ntl) { CP_WAIT0(); __syncthreads(); }
    }

    // ---- epilogue: normalize, split to bf16 hi/lo for the proj GEMM ----
    const float inv0 = 1.0f / l0, inv1 = 1.0f / l1;
    const int qg0 = i0, qg1 = i1;
    #pragma unroll
    for (int nt = 0; nt < 8; nt++) {
        const int d0 = nt * 8 + 2 * q4;
        if (qg0 < Sq) {
            uint32_t hu, lu;
            split2(o[nt][0] * inv0, o[nt][1] * inv0, hu, lu);
            const size_t off = ((size_t)(bSq + qg0)) * EMB + h * HD + d0;
            *(uint32_t*)&g_AOhi[off] = hu;
            *(uint32_t*)&g_AOlo[off] = lu;
        }
        if (qg1 < Sq) {
            uint32_t hu, lu;
            split2(o[nt][2] * inv1, o[nt][3] * inv1, hu, lu);
            const size_t off = ((size_t)(bSq + qg1)) * EMB + h * HD + d0;
            *(uint32_t*)&g_AOhi[off] = hu;
            *(uint32_t*)&g_AOlo[off] = lu;
        }
    }
}

// =====================================================================
// launch  (gemm_mma qkv deliberately placed 4th: that's the ncu slot)
// =====================================================================
extern "C" void kernel_launch(void* const* d_in, const int* in_sizes, int n_in,
                              void* d_out, int out_size)
{
    const float* word = (const float*)d_in[0];
    const float* img  = (const float*)d_in[1];
    const float* am   = (const float*)d_in[2];
    const float* caw  = (const float*)d_in[3];
    const float* cab  = (const float*)d_in[4];
    const float* cpw  = (const float*)d_in[5];
    const float* cpb  = (const float*)d_in[6];
    const float* ukw  = (const float*)d_in[7];
    const float* ukb  = (const float*)d_in[8];
    const float* uvw  = (const float*)d_in[9];
    const float* uvb  = (const float*)d_in[10];
    float* out = (float*)d_out;

    cudaFuncSetAttribute(attn_kernel,
                         cudaFuncAttributeMaxDynamicSharedMemorySize, ATTN_SMEM);
    cudaFuncSetAttribute(gemm_mma_kernel,
                         cudaFuncAttributeMaxDynamicSharedMemorySize, GSMEM);

    conva_kernel<<<MPAD * EMB / 4 / 256, 256>>>(word);           // 1
    wconv_kernel<<<dim3(96, 32), dim3(32, 8)>>>(caw, 3 * EMB, 0);// 2
    pad_ao_kernel<<<16, 256>>>();                                // 3
    gemm_mma_kernel<<<dim3(24, 32), 256, GSMEM>>>(cab, out, 0);  // 4  <- profiled
    wconv_kernel<<<dim3(32, 32), dim3(32, 8)>>>(cpw, EMB, 1);    // 5
    imgkv_kernel<<<1024, 256>>>(img, ukw, ukb, uvw, uvb);        // 6
    attn_kernel<<<dim3(16, NH, Bq), 128, ATTN_SMEM>>>(am);       // 7
    gemm_mma_kernel<<<dim3(8, 32), 256, GSMEM>>>(cpb, out, 1);   // 8
}

// round 14
// speedup vs baseline: 1.1955x; 1.1955x over previous
#include <cuda_runtime.h>
#include <cuda_bf16.h>
#include <cuda_fp16.h>
#include <cstdint>

// Problem constants
#define Bq   4
#define Sq   1023
#define SK   1024
#define EMB  1024
#define NH   16
#define HD   64
#define MTOT (Bq*Sq)        // 4092
#define MPAD 4096

// -------- scratch (device globals; no runtime allocation allowed) --------
__device__ __nv_bfloat16 g_Ahi [MPAD*EMB],   g_Alo [MPAD*EMB];    // word states
__device__ __nv_bfloat16 g_Wqhi[3*EMB*EMB],  g_Wqlo[3*EMB*EMB];   // c_attn_w^T  [n][k]
__device__ __half        g_Wpf [EMB*EMB];                         // c_proj_w^T  fp16
__device__ __half        g_AOf [MPAD*EMB];                        // attn output fp16
// Q/K bf16 hi/lo (softmax-sensitive), V fp16 single
__device__ __nv_bfloat16 g_Qh[Bq*NH*Sq*HD],  g_Ql[Bq*NH*Sq*HD];
__device__ __nv_bfloat16 g_Kh[Bq*NH*SK*HD],  g_Kl[Bq*NH*SK*HD];
__device__ __half        g_Vf[Bq*NH*SK*HD];

// ===================== PTX helpers (compute_103-safe: sm_80 era) =====================
__device__ __forceinline__ uint32_t smem_u32(const void* p) {
    uint32_t a;
    asm("{ .reg .u64 t; cvta.to.shared.u64 t, %1; cvt.u32.u64 %0, t; }"
        : "=r"(a) : "l"(p));
    return a;
}

__device__ __forceinline__ void cp16(uint32_t dst, const void* src) {
    asm volatile("cp.async.cg.shared.global [%0], [%1], 16;"
                 :: "r"(dst), "l"(src) : "memory");
}
__device__ __forceinline__ void cp16z(uint32_t dst, const void* src, bool v) {
    int sz = v ? 16 : 0;
    asm volatile("cp.async.cg.shared.global [%0], [%1], 16, %2;"
                 :: "r"(dst), "l"(src), "r"(sz) : "memory");
}
#define CP_COMMIT() asm volatile("cp.async.commit_group;" ::: "memory")
#define CP_WAIT0()  asm volatile("cp.async.wait_group 0;" ::: "memory")

__device__ __forceinline__ void ldm4(uint32_t* r, uint32_t addr) {
    asm volatile("ldmatrix.sync.aligned.m8n8.x4.shared.b16 {%0,%1,%2,%3}, [%4];"
                 : "=r"(r[0]), "=r"(r[1]), "=r"(r[2]), "=r"(r[3]) : "r"(addr));
}
__device__ __forceinline__ void ldm4t(uint32_t* r, uint32_t addr) {
    asm volatile("ldmatrix.sync.aligned.m8n8.x4.trans.shared.b16 {%0,%1,%2,%3}, [%4];"
                 : "=r"(r[0]), "=r"(r[1]), "=r"(r[2]), "=r"(r[3]) : "r"(addr));
}

__device__ __forceinline__ void mma16816(float* c, const uint32_t* a, const uint32_t* b) {
    asm volatile(
        "mma.sync.aligned.m16n8k16.row.col.f32.bf16.bf16.f32 "
        "{%0,%1,%2,%3}, {%4,%5,%6,%7}, {%8,%9}, {%0,%1,%2,%3};"
        : "+f"(c[0]), "+f"(c[1]), "+f"(c[2]), "+f"(c[3])
        : "r"(a[0]), "r"(a[1]), "r"(a[2]), "r"(a[3]), "r"(b[0]), "r"(b[1]));
}
__device__ __forceinline__ void mma16816h(float* c, const uint32_t* a, const uint32_t* b) {
    asm volatile(
        "mma.sync.aligned.m16n8k16.row.col.f32.f16.f16.f32 "
        "{%0,%1,%2,%3}, {%4,%5,%6,%7}, {%8,%9}, {%0,%1,%2,%3};"
        : "+f"(c[0]), "+f"(c[1]), "+f"(c[2]), "+f"(c[3])
        : "r"(a[0]), "r"(a[1]), "r"(a[2]), "r"(a[3]), "r"(b[0]), "r"(b[1]));
}

// fast e^x on the FMA pipe (x <= ~0; rel err ~2e-6)
__device__ __forceinline__ float fexp(float x) {
    float y = fmaxf(x * 1.4426950408889634f, -126.0f);
    int   n = __float2int_rn(y);
    float f = y - (float)n;
    float p = 1.3333558146e-3f;
    p = fmaf(p, f, 9.6181291076e-3f);
    p = fmaf(p, f, 5.5504108664e-2f);
    p = fmaf(p, f, 2.4022650696e-1f);
    p = fmaf(p, f, 6.9314718056e-1f);
    p = fmaf(p, f, 1.0f);
    return p * __int_as_float((n + 127) << 23);
}

__device__ __forceinline__ void split2(float a, float b, uint32_t& hi, uint32_t& lo) {
    __nv_bfloat162 h = __floats2bfloat162_rn(a, b);
    __nv_bfloat162 l = __floats2bfloat162_rn(a - __bfloat162float(h.x),
                                             b - __bfloat162float(h.y));
    hi = *(uint32_t*)&h;
    lo = *(uint32_t*)&l;
}
__device__ __forceinline__ uint32_t pack_h2(float a, float b) {
    __half2 h = __floats2half2_rn(a, b);
    return *(uint32_t*)&h;
}

// =====================================================================
// Convert kernels
// =====================================================================
__global__ __launch_bounds__(256)
void conva_kernel(const float* __restrict__ word)
{
    const int idx = blockIdx.x * 256 + threadIdx.x;
    const int m = idx >> 8;
    const int c = (idx & 255) * 4;
    float4 v = make_float4(0.f, 0.f, 0.f, 0.f);
    if (m < MTOT) v = *(const float4*)&word[(size_t)m * EMB + c];
    const size_t o = (size_t)m * EMB + c;
    uint32_t h0, l0, h1, l1;
    split2(v.x, v.y, h0, l0);
    split2(v.z, v.w, h1, l1);
    *(uint32_t*)&g_Ahi[o]     = h0;
    *(uint32_t*)&g_Ahi[o + 2] = h1;
    *(uint32_t*)&g_Alo[o]     = l0;
    *(uint32_t*)&g_Alo[o + 2] = l1;
}

// transpose + convert: W[K=1024][N] -> mode0: Wq bf16 hi/lo; mode1: Wp fp16
__global__ __launch_bounds__(256)
void wconv_kernel(const float* __restrict__ W, int N, int mode)
{
    __shared__ float t[32][33];
    const int nx = blockIdx.x * 32, ky = blockIdx.y * 32;
    const int tx = threadIdx.x, ty = threadIdx.y;
    #pragma unroll
    for (int i = 0; i < 32; i += 8)
        t[ty + i][tx] = W[(size_t)(ky + ty + i) * N + nx + tx];
    __syncthreads();
    #pragma unroll
    for (int i = 0; i < 32; i += 8) {
        const float v = t[tx][ty + i];
        const int n = nx + ty + i, k = ky + tx;
        if (mode) {
            g_Wpf[(size_t)n * EMB + k] = __float2half(v);
        } else {
            const __nv_bfloat16 h = __float2bfloat16(v);
            g_Wqhi[(size_t)n * EMB + k] = h;
            g_Wqlo[(size_t)n * EMB + k] = __float2bfloat16(v - __bfloat162float(h));
        }
    }
}

__global__ __launch_bounds__(256)
void pad_ao_kernel()
{
    const int i = blockIdx.x * 256 + threadIdx.x;
    if (i < (MPAD - MTOT) * EMB)
        g_AOf[(size_t)MTOT * EMB + i] = __float2half(0.f);
}

// =====================================================================
// qkv GEMM: bf16 3-pass split, 128x128 tile, BK=32, 2-stage (R12 config).
// Epilogue scatters Q/K bf16 hi/lo, V fp16.
// =====================================================================
#define GBK   32
#define GSTR  40
#define MATB  (128 * GSTR * 2)
#define BUFB  (4 * MATB)             // 40960
#define GSMEM (2 * BUFB)             // 81920
#define NCH   (EMB / GBK)

__device__ __forceinline__ void gload(uint32_t dstbase, int tid, int k0, int bm, int bn)
{
    #pragma unroll
    for (int t = 0; t < 8; t++) {
        const int i   = tid + t * 256;
        const int mat = i >> 9;
        const int r   = (i >> 2) & 127;
        const int seg = i & 3;
        const uint32_t dst = dstbase + mat * MATB + r * (GSTR * 2) + seg * 16;
        const __nv_bfloat16* src = (mat == 0) ? g_Ahi : (mat == 1) ? g_Alo
                                 : (mat == 2) ? g_Wqhi : g_Wqlo;
        const int grow = ((mat < 2) ? bm : bn) + r;
        cp16(dst, src + (size_t)grow * EMB + k0 + seg * 8);
    }
    CP_COMMIT();
}

__global__ __launch_bounds__(256)
void gemm_mma_kernel(const float* __restrict__ bias)
{
    extern __shared__ __nv_bfloat16 smg[];
    const uint32_t sb = smem_u32(smg);

    const int tid  = threadIdx.x;
    const int warp = tid >> 5;
    const int lane = tid & 31;
    const int bn = blockIdx.x * 128;
    const int bm = blockIdx.y * 128;
    const int wm = (warp & 3) * 32;
    const int wn = (warp >> 2) * 64;

    float acc[2][8][4];
    #pragma unroll
    for (int i = 0; i < 2; i++)
        #pragma unroll
        for (int j = 0; j < 8; j++)
            #pragma unroll
            for (int k = 0; k < 4; k++) acc[i][j][k] = 0.0f;

    gload(sb, tid, 0, bm, bn);

    for (int c = 0; c < NCH; c++) {
        CP_WAIT0();
        __syncthreads();
        if (c + 1 < NCH)
            gload(sb + ((c + 1) & 1) * BUFB, tid, (c + 1) * GBK, bm, bn);

        const uint32_t cb = sb + (c & 1) * BUFB;

        #pragma unroll
        for (int ks = 0; ks < GBK; ks += 16) {
            uint32_t ahi[2][4], alo[2][4], bhi[8][2], blo[8][2];
            #pragma unroll
            for (int mt = 0; mt < 2; mt++) {
                const uint32_t ra = cb + (wm + mt * 16 + (lane & 15)) * (GSTR * 2)
                                       + (ks + (lane >> 4) * 8) * 2;
                ldm4(ahi[mt], ra);
                ldm4(alo[mt], ra + MATB);
            }
            #pragma unroll
            for (int p = 0; p < 4; p++) {
                const uint32_t rowb = wn + p * 16 + (lane & 7) + ((lane >> 4) << 3);
                const uint32_t rb = cb + 2 * MATB + rowb * (GSTR * 2)
                                       + (ks + ((lane >> 3) & 1) * 8) * 2;
                uint32_t r4[4];
                ldm4(r4, rb);
                bhi[p*2][0] = r4[0]; bhi[p*2][1] = r4[1];
                bhi[p*2+1][0] = r4[2]; bhi[p*2+1][1] = r4[3];
                ldm4(r4, rb + MATB);
                blo[p*2][0] = r4[0]; blo[p*2][1] = r4[1];
                blo[p*2+1][0] = r4[2]; blo[p*2+1][1] = r4[3];
            }
            #pragma unroll
            for (int mt = 0; mt < 2; mt++)
                #pragma unroll
                for (int nt = 0; nt < 8; nt++) {
                    mma16816(acc[mt][nt], ahi[mt], bhi[nt]);
                    mma16816(acc[mt][nt], alo[mt], bhi[nt]);
                    mma16816(acc[mt][nt], ahi[mt], blo[nt]);
                }
        }
    }

    // ---- epilogue: scatter Q/K bf16 hi/lo, V fp16 ----
    #pragma unroll
    for (int mt = 0; mt < 2; mt++) {
        #pragma unroll
        for (int nt = 0; nt < 8; nt++) {
            const int n = bn + wn + nt * 8 + (lane & 3) * 2;
            const float2 bv = *(const float2*)&bias[n];
            #pragma unroll
            for (int half_ = 0; half_ < 2; half_++) {
                const int m = bm + wm + mt * 16 + (lane >> 2) + half_ * 8;
                if (m >= MTOT) continue;
                float2 v = make_float2(acc[mt][nt][half_*2+0] + bv.x,
                                       acc[mt][nt][half_*2+1] + bv.y);
                const int b_ = m / Sq;
                const int s  = m - b_ * Sq;
                const int sec = n >> 10;
                const int e = n & 1023, h = e >> 6, d = e & 63;
                if (sec == 2) {
                    const size_t off = ((size_t)(b_ * NH + h) * SK + s + 1) * HD + d;
                    *(uint32_t*)&g_Vf[off] = pack_h2(v.x, v.y);
                } else {
                    uint32_t hu, lu;
                    split2(v.x, v.y, hu, lu);
                    if (sec == 0) {
                        const size_t off = ((size_t)(b_ * NH + h) * Sq + s) * HD + d;
                        *(uint32_t*)&g_Qh[off] = hu;
                        *(uint32_t*)&g_Ql[off] = lu;
                    } else {
                        const size_t off = ((size_t)(b_ * NH + h) * SK + s + 1) * HD + d;
                        *(uint32_t*)&g_Kh[off] = hu;
                        *(uint32_t*)&g_Kl[off] = lu;
                    }
                }
            }
        }
    }
}

// =====================================================================
// proj GEMM: fp16 single-pass, 128x128 tile, BK=32, 2-stage.
// =====================================================================
#define PBUFB (2 * MATB)             // 20480
#define PSMEM (2 * PBUFB)            // 40960

__device__ __forceinline__ void pload(uint32_t dstbase, int tid, int k0, int bm, int bn)
{
    #pragma unroll
    for (int t = 0; t < 4; t++) {
        const int i   = tid + t * 256;      // 0..1023
        const int mat = i >> 9;             // 0..1
        const int r   = (i >> 2) & 127;
        const int seg = i & 3;
        const uint32_t dst = dstbase + mat * MATB + r * (GSTR * 2) + seg * 16;
        const __half* src = mat ? g_Wpf : g_AOf;
        const int grow = (mat ? bn : bm) + r;
        cp16(dst, src + (size_t)grow * EMB + k0 + seg * 8);
    }
    CP_COMMIT();
}

__global__ __launch_bounds__(256)
void pgemm_kernel(const float* __restrict__ bias, float* __restrict__ out)
{
    extern __shared__ __half smp[];
    const uint32_t sb = smem_u32(smp);

    const int tid  = threadIdx.x;
    const int warp = tid >> 5;
    const int lane = tid & 31;
    const int bn = blockIdx.x * 128;
    const int bm = blockIdx.y * 128;
    const int wm = (warp & 3) * 32;
    const int wn = (warp >> 2) * 64;

    float acc[2][8][4];
    #pragma unroll
    for (int i = 0; i < 2; i++)
        #pragma unroll
        for (int j = 0; j < 8; j++)
            #pragma unroll
            for (int k = 0; k < 4; k++) acc[i][j][k] = 0.0f;

    pload(sb, tid, 0, bm, bn);

    for (int c = 0; c < NCH; c++) {
        CP_WAIT0();
        __syncthreads();
        if (c + 1 < NCH)
            pload(sb + ((c + 1) & 1) * PBUFB, tid, (c + 1) * GBK, bm, bn);

        const uint32_t cb = sb + (c & 1) * PBUFB;

        #pragma unroll
        for (int ks = 0; ks < GBK; ks += 16) {
            uint32_t a[2][4], bb[8][2];
            #pragma unroll
            for (int mt = 0; mt < 2; mt++)
                ldm4(a[mt], cb + (wm + mt * 16 + (lane & 15)) * (GSTR * 2)
                               + (ks + (lane >> 4) * 8) * 2);
            #pragma unroll
            for (int p = 0; p < 4; p++) {
                const uint32_t rowb = wn + p * 16 + (lane & 7) + ((lane >> 4) << 3);
                uint32_t r4[4];
                ldm4(r4, cb + MATB + rowb * (GSTR * 2)
                               + (ks + ((lane >> 3) & 1) * 8) * 2);
                bb[p*2][0] = r4[0]; bb[p*2][1] = r4[1];
                bb[p*2+1][0] = r4[2]; bb[p*2+1][1] = r4[3];
            }
            #pragma unroll
            for (int mt = 0; mt < 2; mt++)
                #pragma unroll
                for (int nt = 0; nt < 8; nt++)
                    mma16816h(acc[mt][nt], a[mt], bb[nt]);
        }
    }

    #pragma unroll
    for (int mt = 0; mt < 2; mt++) {
        #pragma unroll
        for (int nt = 0; nt < 8; nt++) {
            const int n = bn + wn + nt * 8 + (lane & 3) * 2;
            const float2 bv = *(const float2*)&bias[n];
            #pragma unroll
            for (int half_ = 0; half_ < 2; half_++) {
                const int m = bm + wm + mt * 16 + (lane >> 2) + half_ * 8;
                if (m >= MTOT) continue;
                float2 v = make_float2(acc[mt][nt][half_*2+0] + bv.x,
                                       acc[mt][nt][half_*2+1] + bv.y);
                *(float2*)&out[(size_t)m * EMB + n] = v;
            }
        }
    }
}

// =====================================================================
// image k/v -> slot 0: K bf16 hi/lo, V fp16
// =====================================================================
__global__ __launch_bounds__(256)
void imgkv_kernel(const float* __restrict__ img,
                  const float* __restrict__ ukw, const float* __restrict__ ukb,
                  const float* __restrict__ uvw, const float* __restrict__ uvb)
{
    const int warp = threadIdx.x >> 5;
    const int lane = threadIdx.x & 31;
    const int idx  = blockIdx.x * 8 + warp;
    const int kv   = idx >> 12;
    const int rem  = idx & 4095;
    const int b    = rem >> 10;
    const int e    = rem & 1023;

    const float* w = (kv == 0 ? ukw : uvw) + (size_t)e * EMB;
    const float* x = img + (size_t)b * EMB;

    float s = 0.0f;
    #pragma unroll
    for (int t = 0; t < 8; t++) {
        const int f = (lane + t * 32) * 4;
        float4 wv = *(const float4*)&w[f];
        float4 xv = *(const float4*)&x[f];
        s = fmaf(wv.x, xv.x, s);
        s = fmaf(wv.y, xv.y, s);
        s = fmaf(wv.z, xv.z, s);
        s = fmaf(wv.w, xv.w, s);
    }
    #pragma unroll
    for (int off = 16; off >= 1; off >>= 1)
        s += __shfl_xor_sync(0xffffffffu, s, off, 32);

    if (lane == 0) {
        const float v = s + (kv == 0 ? ukb : uvb)[e];
        const int h = e >> 6, d = e & 63;
        const size_t off = ((size_t)(b * NH + h) * SK + 0) * HD + d;
        if (kv == 0) {
            const __nv_bfloat16 hh = __float2bfloat16(v);
            g_Kh[off] = hh;
            g_Kl[off] = __float2bfloat16(v - __bfloat162float(hh));
        } else {
            g_Vf[off] = __float2half(v);
        }
    }
}

// =====================================================================
// tensor-core flash attention: QK^T bf16 3-pass, PV fp16 single-pass.
// CTA: 128 threads = 4 warps, 64 queries; stream 64-key tiles.
// smem: Qhi|Qlo | 2 x {Khi,Klo,Vf}; stride 72.
// =====================================================================
#define ASTR    72
#define ATILE_B (64 * ASTR * 2)      // 9216
#define ATTN_SMEM (8 * ATILE_B)      // 73728

__device__ __forceinline__ void attn_ldkv(uint32_t dst, int tid, int kb,
    const __nv_bfloat16* __restrict__ Khp, const __nv_bfloat16* __restrict__ Klp,
    const __half* __restrict__ Vfp)
{
    #pragma unroll
    for (int t = 0; t < 12; t++) {
        const int i   = tid + t * 128;      // 0..1535
        const int mat = i >> 9;             // 0..2
        const int r   = (i >> 3) & 63;
        const int seg = i & 7;
        const char* src = (mat == 0) ? (const char*)(Khp + (size_t)(kb + r) * HD + seg * 8)
                        : (mat == 1) ? (const char*)(Klp + (size_t)(kb + r) * HD + seg * 8)
                                     : (const char*)(Vfp + (size_t)(kb + r) * HD + seg * 8);
        cp16(dst + mat * ATILE_B + r * (ASTR * 2) + seg * 16, src);
    }
    CP_COMMIT();
}

__global__ __launch_bounds__(128)
void attn_kernel(const float* __restrict__ am)
{
    extern __shared__ char smA[];
    const uint32_t sb = smem_u32(smA);

    const int b  = blockIdx.z;
    const int h  = blockIdx.y;
    const int qt = (int)(gridDim.x - 1) - (int)blockIdx.x;   // heavy tiles first
    const int tid  = threadIdx.x;
    const int warp = tid >> 5;
    const int lane = tid & 31;
    const int q4 = lane & 3;
    const int r8 = lane >> 2;
    const int wm = warp * 16;
    const int q0 = qt * 64;
    const int bh = b * NH + h;
    const int bSq = b * Sq;

    const __nv_bfloat16* Khp = g_Kh + (size_t)bh * SK * HD;
    const __nv_bfloat16* Klp = g_Kl + (size_t)bh * SK * HD;
    const __half*        Vfp = g_Vf + (size_t)bh * SK * HD;

    // --- load Q tile (hi/lo) + first K/V tile ---
    #pragma unroll
    for (int t = 0; t < 8; t++) {
        const int i   = tid + t * 128;      // 0..1023
        const int mat = i >> 9;             // 0..1
        const int r   = (i >> 3) & 63;
        const int seg = i & 7;
        const int row = q0 + r;
        const bool v = row < Sq;
        const __nv_bfloat16* src = (mat ? g_Ql : g_Qh)
            + ((size_t)bh * Sq + (v ? row : 0)) * HD + seg * 8;
        cp16z(sb + mat * ATILE_B + r * (ASTR * 2) + seg * 16, src, v);
    }
    attn_ldkv(sb + 2 * ATILE_B, tid, 0, Khp, Klp, Vfp);
    CP_WAIT0();
    __syncthreads();

    // Q fragments (A operand, m16k16 x4 ksteps), loaded once
    uint32_t qhi[4][4], qlo[4][4];
    #pragma unroll
    for (int kk = 0; kk < 4; kk++) {
        const uint32_t ra = sb + (wm + (lane & 15)) * (ASTR * 2)
                               + (kk * 16 + (lane >> 4) * 8) * 2;
        ldm4(qhi[kk], ra);
        ldm4(qlo[kk], ra + ATILE_B);
    }

    float o[8][4];
    #pragma unroll
    for (int i = 0; i < 8; i++)
        #pragma unroll
        for (int j = 0; j < 4; j++) o[i][j] = 0.0f;
    float m0 = -1e30f, m1 = -1e30f, l0 = 0.0f, l1 = 0.0f;

    const int ntl = min(16, qt + 2);
    const int i0 = q0 + wm + r8;
    const int i1 = i0 + 8;

    for (int c = 0; c < ntl; c++) {
        const uint32_t B0 = sb + 2 * ATILE_B + (c & 1) * (3 * ATILE_B);
        if (c + 1 < ntl)
            attn_ldkv(sb + 2 * ATILE_B + ((c + 1) & 1) * (3 * ATILE_B),
                      tid, (c + 1) * 64, Khp, Klp, Vfp);
        const int kb = c * 64;

        // ---- S = Q K^T (3-pass bf16 split) ----
        float s[8][4];
        #pragma unroll
        for (int i = 0; i < 8; i++)
            #pragma unroll
            for (int j = 0; j < 4; j++) s[i][j] = 0.0f;

        #pragma unroll
        for (int kk = 0; kk < 4; kk++) {
            uint32_t kbh[8][2], kbl[8][2];
            #pragma unroll
            for (int p = 0; p < 4; p++) {
                const uint32_t rb = B0
                    + (p * 16 + (lane & 7) + ((lane >> 4) << 3)) * (ASTR * 2)
                    + (kk * 16 + ((lane >> 3) & 1) * 8) * 2;
                uint32_t r4[4];
                ldm4(r4, rb);
                kbh[p*2][0] = r4[0]; kbh[p*2][1] = r4[1];
                kbh[p*2+1][0] = r4[2]; kbh[p*2+1][1] = r4[3];
                ldm4(r4, rb + ATILE_B);
                kbl[p*2][0] = r4[0]; kbl[p*2][1] = r4[1];
                kbl[p*2+1][0] = r4[2]; kbl[p*2+1][1] = r4[3];
            }
            #pragma unroll
            for (int nt = 0; nt < 8; nt++) {
                mma16816(s[nt], qhi[kk], kbh[nt]);
                mma16816(s[nt], qlo[kk], kbh[nt]);
                mma16816(s[nt], qhi[kk], kbl[nt]);
            }
        }

        // ---- scale + mask + online softmax ----
        const bool domask = (c >= qt);
        float tm0 = -1e30f, tm1 = -1e30f;
        #pragma unroll
        for (int nt = 0; nt < 8; nt++) {
            const int j0 = kb + nt * 8 + 2 * q4;
            const float a0 = (j0 == 0) ? 0.0f : am[bSq + j0 - 1];
            const float a1 = am[bSq + j0];
            float v0 = fmaf(s[nt][0], 0.125f, a0);
            float v1 = fmaf(s[nt][1], 0.125f, a1);
            float v2 = fmaf(s[nt][2], 0.125f, a0);
            float v3 = fmaf(s[nt][3], 0.125f, a1);
            if (domask) {
                if (j0     > i0 + 1) v0 = -10000.0f + a0;
                if (j0 + 1 > i0 + 1) v1 = -10000.0f + a1;
                if (j0     > i1 + 1) v2 = -10000.0f + a0;
                if (j0 + 1 > i1 + 1) v3 = -10000.0f + a1;
            }
            s[nt][0] = v0; s[nt][1] = v1; s[nt][2] = v2; s[nt][3] = v3;
            tm0 = fmaxf(tm0, fmaxf(v0, v1));
            tm1 = fmaxf(tm1, fmaxf(v2, v3));
        }
        tm0 = fmaxf(tm0, __shfl_xor_sync(0xffffffffu, tm0, 1, 32));
        tm0 = fmaxf(tm0, __shfl_xor_sync(0xffffffffu, tm0, 2, 32));
        tm1 = fmaxf(tm1, __shfl_xor_sync(0xffffffffu, tm1, 1, 32));
        tm1 = fmaxf(tm1, __shfl_xor_sync(0xffffffffu, tm1, 2, 32));

        const float nm0 = fmaxf(m0, tm0), nm1 = fmaxf(m1, tm1);
        const float cor0 = fexp(m0 - nm0), cor1 = fexp(m1 - nm1);
        m0 = nm0; m1 = nm1;

        float rs0 = 0.0f, rs1 = 0.0f;
        #pragma unroll
        for (int nt = 0; nt < 8; nt++) {
            s[nt][0] = fexp(s[nt][0] - m0);
            s[nt][1] = fexp(s[nt][1] - m0);
            s[nt][2] = fexp(s[nt][2] - m1);
            s[nt][3] = fexp(s[nt][3] - m1);
            rs0 += s[nt][0] + s[nt][1];
            rs1 += s[nt][2] + s[nt][3];
        }
        rs0 += __shfl_xor_sync(0xffffffffu, rs0, 1, 32);
        rs0 += __shfl_xor_sync(0xffffffffu, rs0, 2, 32);
        rs1 += __shfl_xor_sync(0xffffffffu, rs1, 1, 32);
        rs1 += __shfl_xor_sync(0xffffffffu, rs1, 2, 32);
        l0 = l0 * cor0 + rs0;
        l1 = l1 * cor1 + rs1;
        #pragma unroll
        for (int nt = 0; nt < 8; nt++) {
            o[nt][0] *= cor0; o[nt][1] *= cor0;
            o[nt][2] *= cor1; o[nt][3] *= cor1;
        }

        // ---- pack P into fp16 A fragments (single) ----
        uint32_t pf[4][4];
        #pragma unroll
        for (int kk = 0; kk < 4; kk++) {
            pf[kk][0] = pack_h2(s[2*kk][0],   s[2*kk][1]);
            pf[kk][1] = pack_h2(s[2*kk][2],   s[2*kk][3]);
            pf[kk][2] = pack_h2(s[2*kk+1][0], s[2*kk+1][1]);
            pf[kk][3] = pack_h2(s[2*kk+1][2], s[2*kk+1][3]);
        }

        // ---- O += P V (fp16 single-pass), V via ldmatrix.trans ----
        const uint32_t Vb = B0 + 2 * ATILE_B;
        #pragma unroll
        for (int kk = 0; kk < 4; kk++) {
            #pragma unroll
            for (int np = 0; np < 4; np++) {
                const uint32_t va = Vb + (kk * 16 + (lane & 15)) * (ASTR * 2)
                                       + (np * 16 + (lane >> 4) * 8) * 2;
                uint32_t r4[4];
                ldm4t(r4, va);
                uint32_t b0[2] = { r4[0], r4[1] };
                uint32_t b1[2] = { r4[2], r4[3] };
                mma16816h(o[np*2],   pf[kk], b0);
                mma16816h(o[np*2+1], pf[kk], b1);
            }
        }

        if (c + 1 < ntl) { CP_WAIT0(); __syncthreads(); }
    }

    // ---- epilogue: normalize, write fp16 AO for the proj GEMM ----
    const float inv0 = 1.0f / l0, inv1 = 1.0f / l1;
    #pragma unroll
    for (int nt = 0; nt < 8; nt++) {
        const int d0 = nt * 8 + 2 * q4;
        if (i0 < Sq) {
            const size_t off = ((size_t)(bSq + i0)) * EMB + h * HD + d0;
            *(uint32_t*)&g_AOf[off] = pack_h2(o[nt][0] * inv0, o[nt][1] * inv0);
        }
        if (i1 < Sq) {
            const size_t off = ((size_t)(bSq + i1)) * EMB + h * HD + d0;
            *(uint32_t*)&g_AOf[off] = pack_h2(o[nt][2] * inv1, o[nt][3] * inv1);
        }
    }
}

// =====================================================================
// launch  (qkv gemm kept in ncu slot 4)
// =====================================================================
extern "C" void kernel_launch(void* const* d_in, const int* in_sizes, int n_in,
                              void* d_out, int out_size)
{
    const float* word = (const float*)d_in[0];
    const float* img  = (const float*)d_in[1];
    const float* am   = (const float*)d_in[2];
    const float* caw  = (const float*)d_in[3];
    const float* cab  = (const float*)d_in[4];
    const float* cpw  = (const float*)d_in[5];
    const float* cpb  = (const float*)d_in[6];
    const float* ukw  = (const float*)d_in[7];
    const float* ukb  = (const float*)d_in[8];
    const float* uvw  = (const float*)d_in[9];
    const float* uvb  = (const float*)d_in[10];
    float* out = (float*)d_out;

    cudaFuncSetAttribute(attn_kernel,
                         cudaFuncAttributeMaxDynamicSharedMemorySize, ATTN_SMEM);
    cudaFuncSetAttribute(gemm_mma_kernel,
                         cudaFuncAttributeMaxDynamicSharedMemorySize, GSMEM);

    conva_kernel<<<MPAD * EMB / 4 / 256, 256>>>(word);           // 1
    wconv_kernel<<<dim3(96, 32), dim3(32, 8)>>>(caw, 3 * EMB, 0);// 2
    pad_ao_kernel<<<16, 256>>>();                                // 3
    gemm_mma_kernel<<<dim3(24, 32), 256, GSMEM>>>(cab);          // 4  <- profiled
    wconv_kernel<<<dim3(32, 32), dim3(32, 8)>>>(cpw, EMB, 1);    // 5
    imgkv_kernel<<<1024, 256>>>(img, ukw, ukb, uvw, uvb);        // 6
    attn_kernel<<<dim3(16, NH, Bq), 128, ATTN_SMEM>>>(am);       // 7
    pgemm_kernel<<<dim3(8, 32), 256, PSMEM>>>(cpb, out);         // 8
}